// round 11
// baseline (speedup 1.0000x reference)
#include <cuda_runtime.h>
#include <cstdint>

// Problem constants
#define Bb 2
#define Ss 2048
#define Dd 512
#define Hh 8
#define DHd 64
#define BSr (Bb*Ss)     // 4096 rows

// ---------------------------------------------------------------------------
// Pre-split bf16 hi/lo device buffers (u32 = bf16x2 word for an element pair).
// Row layouts:
//   g_Xbf/g_Wbf/g_Wobf/g_Obf: [row][512]  -> hi words [0:256), lo words [256:512)
//   g_Qbf/g_Kbf/g_Vbf: [(h*Bb+b)*Ss + s][64] -> hi words [0:32), lo [32:64)
// ---------------------------------------------------------------------------
__device__ __align__(16) uint32_t g_Xbf [4096*512];
__device__ __align__(16) uint32_t g_Wbf [1536*512];
__device__ __align__(16) uint32_t g_Wobf[512*512];
__device__ __align__(16) uint32_t g_Obf [4096*512];
__device__ __align__(16) uint32_t g_Qbf [Hh*Bb*Ss*64];
__device__ __align__(16) uint32_t g_Kbf [Hh*Bb*Ss*64];
__device__ __align__(16) uint32_t g_Vbf [Hh*Bb*Ss*64];

// ---------------------------------------------------------------------------
// helpers
// ---------------------------------------------------------------------------
__device__ __forceinline__ void mma_bf16(float* d, const uint32_t* a,
                                         uint32_t b0, uint32_t b1) {
    asm volatile("mma.sync.aligned.m16n8k16.row.col.f32.bf16.bf16.f32 "
                 "{%0,%1,%2,%3}, {%4,%5,%6,%7}, {%8,%9}, {%0,%1,%2,%3};"
                 : "+f"(d[0]), "+f"(d[1]), "+f"(d[2]), "+f"(d[3])
                 : "r"(a[0]), "r"(a[1]), "r"(a[2]), "r"(a[3]), "r"(b0), "r"(b1));
}
__device__ __forceinline__ void ldsm4(uint32_t* r, uint32_t a) {
    asm volatile("ldmatrix.sync.aligned.m8n8.x4.shared.b16 {%0,%1,%2,%3}, [%4];"
                 : "=r"(r[0]), "=r"(r[1]), "=r"(r[2]), "=r"(r[3]) : "r"(a));
}
__device__ __forceinline__ void ldsm4t(uint32_t* r, uint32_t a) {
    asm volatile("ldmatrix.sync.aligned.m8n8.x4.trans.shared.b16 {%0,%1,%2,%3}, [%4];"
                 : "=r"(r[0]), "=r"(r[1]), "=r"(r[2]), "=r"(r[3]) : "r"(a));
}
__device__ __forceinline__ uint32_t smem_u32(const void* p) {
    uint32_t a;
    asm("{ .reg .u64 t; cvta.to.shared.u64 t, %1; cvt.u32.u64 %0, t; }"
        : "=r"(a) : "l"(p));
    return a;
}
__device__ __forceinline__ uint32_t bf2(float hi, float lo) {
    uint32_t r;
    asm("cvt.rn.bf16x2.f32 %0, %1, %2;" : "=r"(r) : "f"(hi), "f"(lo));
    return r;
}
__device__ __forceinline__ float bflo_f(uint32_t w) { return __uint_as_float(w << 16); }
__device__ __forceinline__ float bfhi_f(uint32_t w) { return __uint_as_float(w & 0xFFFF0000u); }
__device__ __forceinline__ void split2(float2 f, uint32_t& whi, uint32_t& wlo) {
    whi = bf2(f.y, f.x);
    float rx = f.x - bflo_f(whi);
    float ry = f.y - bfhi_f(whi);
    wlo = bf2(ry, rx);
}
__device__ __forceinline__ void cpa16(uint32_t dst, const uint32_t* src) {
    asm volatile("cp.async.cg.shared.global [%0], [%1], 16;"
                 :: "r"(dst), "l"(src) : "memory");
}
#define CP_COMMIT() asm volatile("cp.async.commit_group;" ::: "memory")
#define CP_WAIT0()  asm volatile("cp.async.wait_group 0;" ::: "memory")

// ---------------------------------------------------------------------------
// Kernel 0: pre-split X, W, Wo into bf16 hi/lo buffers (runs once, ~4us)
// ---------------------------------------------------------------------------
__global__ void presplit(const float* __restrict__ X,
                         const float* __restrict__ W,
                         const float* __restrict__ Wo) {
    for (int idx = blockIdx.x * blockDim.x + threadIdx.x;
         idx < 1572864; idx += gridDim.x * blockDim.x) {
        const float* src; uint32_t* dst; int p;
        if (idx < 1048576)      { p = idx;           src = X;  dst = g_Xbf; }
        else if (idx < 1441792) { p = idx - 1048576; src = W;  dst = g_Wbf; }
        else                    { p = idx - 1441792; src = Wo; dst = g_Wobf; }
        int row = p >> 8, wc = p & 255;
        float2 f = *(const float2*)&src[(size_t)row * 512 + wc * 2];
        uint32_t hi, lo; split2(f, hi, lo);
        dst[(size_t)row * 512 + wc]       = hi;
        dst[(size_t)row * 512 + 256 + wc] = lo;
    }
}

// ---------------------------------------------------------------------------
// Unified bf16x3 GEMM on pre-split inputs: C = A @ B^T + bias, K=512.
// CTA tile 128x128, 8 warps 2(M) x 4(N). K chunks of 64; staging = pure
// cp.async copies. 3 passes: Ah*Bh + Ah*Bl + Al*Bh.
// MODE 0: A=g_Xbf, B=g_Wbf, scatter to g_Qbf/g_Kbf/g_Vbf (pre-split).
// MODE 1: A=g_Obf, B=g_Wobf, write fp32 out.
// ---------------------------------------------------------------------------
#define GSTR 144
#define GEMM_SMEM 73728

template<int MODE>
__global__ __launch_bounds__(256, 2) void tc_gemm(const float* __restrict__ bias,
                                                  float* __restrict__ out) {
    extern __shared__ char smg[];
    const uint32_t sb = smem_u32(smg);
    const int tid = threadIdx.x;
    const int lane = tid & 31;
    const int w = tid >> 5;
    const int g = lane >> 2;
    const int tg = lane & 3;
    const int r8 = lane & 7;
    const int mlo = (lane >> 3) & 1;
    const int mhi = lane >> 4;
    const int bm = blockIdx.y * 128;
    const int bn = blockIdx.x * 128;

    const uint32_t* Aw = (MODE == 0) ? g_Xbf : g_Obf;
    const uint32_t* Bw = (MODE == 0) ? g_Wbf : g_Wobf;

    const int wm = (w >> 2) * 64;
    const int wn = (w & 3) * 32;

    float acc[4][4][4];
#pragma unroll
    for (int mb = 0; mb < 4; mb++)
#pragma unroll
        for (int nb = 0; nb < 4; nb++)
#pragma unroll
            for (int q = 0; q < 4; q++) acc[mb][nb][q] = 0.f;

    const uint32_t aA = sb + 0     + (uint32_t)((wm + mlo * 8 + r8) * GSTR + mhi * 16);
    const uint32_t aB = sb + 36864 + (uint32_t)((wn + mhi * 8 + r8) * GSTR + mlo * 16);

#pragma unroll 1
    for (int c = 0; c < 8; c++) {
        if (c) __syncthreads();
        const int c0w = c * 32;
        // ---- stage chunk via cp.async: A 2048 + B 2048 uint4, 16/thread ----
#pragma unroll
        for (int it = 0; it < 16; it++) {
            int item = tid + it * 256;
            int side = item >> 11;          // 0 = A, 1 = B
            int idx = item & 2047;
            int row = idx >> 4;
            int c4 = idx & 15;
            int hi = c4 >> 3;
            const uint32_t* src = (side ? Bw + (size_t)(bn + row) * 512
                                        : Aw + (size_t)(bm + row) * 512)
                                  + (hi << 8) + c0w + (c4 & 7) * 4;
            uint32_t dst = sb + side * 36864 + hi * 18432
                         + (uint32_t)(row * GSTR + (c4 & 7) * 16);
            cpa16(dst, src);
        }
        CP_COMMIT();
        CP_WAIT0();
        __syncthreads();

        // ---- compute: 4 k16 steps ----
#pragma unroll
        for (int kk = 0; kk < 4; kk++) {
            uint32_t ah[4][4], al[4][4];
#pragma unroll
            for (int mb = 0; mb < 4; mb++) {
                ldsm4(ah[mb], aA + mb * (16 * GSTR) + kk * 32);
                ldsm4(al[mb], aA + 18432 + mb * (16 * GSTR) + kk * 32);
            }
#pragma unroll
            for (int j = 0; j < 2; j++) {
                uint32_t bh[4], bl[4];
                ldsm4(bh, aB + j * (16 * GSTR) + kk * 32);
                ldsm4(bl, aB + 18432 + j * (16 * GSTR) + kk * 32);
#pragma unroll
                for (int mb = 0; mb < 4; mb++) {
                    mma_bf16(acc[mb][2*j],   ah[mb], bh[0], bh[1]);
                    mma_bf16(acc[mb][2*j+1], ah[mb], bh[2], bh[3]);
                    mma_bf16(acc[mb][2*j],   ah[mb], bl[0], bl[1]);
                    mma_bf16(acc[mb][2*j+1], ah[mb], bl[2], bl[3]);
                    mma_bf16(acc[mb][2*j],   al[mb], bh[0], bh[1]);
                    mma_bf16(acc[mb][2*j+1], al[mb], bh[2], bh[3]);
                }
            }
        }
    }

    // ---- epilogue ----
#pragma unroll
    for (int nb = 0; nb < 4; nb++) {
        if (MODE == 0) {
            const int nbb = bn + wn + nb * 8;
            const int h = nbb / 192;
            const int r = nbb - h * 192;
            const int t = r >> 6;
            uint32_t* dst = (t == 0) ? g_Qbf : (t == 1) ? g_Kbf : g_Vbf;
            const int wc = ((r & 63) >> 1) + tg;
            const float2 bia = *(const float2*)&bias[nbb + 2 * tg];
#pragma unroll
            for (int mb = 0; mb < 4; mb++) {
                const int m0 = bm + wm + mb * 16 + g;
                {
                    const int bi = m0 >> 11, ss = m0 & 2047;
                    const size_t base = ((size_t)(h * Bb + bi) * Ss + ss) * 64;
                    uint32_t hi, lo;
                    split2(make_float2(acc[mb][nb][0] + bia.x,
                                       acc[mb][nb][1] + bia.y), hi, lo);
                    dst[base + wc] = hi;
                    dst[base + 32 + wc] = lo;
                }
                {
                    const int m1 = m0 + 8;
                    const int bi = m1 >> 11, ss = m1 & 2047;
                    const size_t base = ((size_t)(h * Bb + bi) * Ss + ss) * 64;
                    uint32_t hi, lo;
                    split2(make_float2(acc[mb][nb][2] + bia.x,
                                       acc[mb][nb][3] + bia.y), hi, lo);
                    dst[base + wc] = hi;
                    dst[base + 32 + wc] = lo;
                }
            }
        } else {
            const int n0 = bn + wn + nb * 8 + 2 * tg;
            const float2 bia = *(const float2*)&bias[n0];
#pragma unroll
            for (int mb = 0; mb < 4; mb++) {
                const int m0 = bm + wm + mb * 16 + g;
                float2 v0; v0.x = acc[mb][nb][0] + bia.x; v0.y = acc[mb][nb][1] + bia.y;
                float2 v1; v1.x = acc[mb][nb][2] + bia.x; v1.y = acc[mb][nb][3] + bia.y;
                *(float2*)&out[(size_t)m0 * 512 + n0] = v0;
                *(float2*)&out[(size_t)(m0 + 8) * 512 + n0] = v1;
            }
        }
    }
}

// ---------------------------------------------------------------------------
// Kernel 2: flash attention, bf16x3 mma. Staging = cp.async copies of
// pre-split Q/K/V tiles. Softmax: p = exp2(t) * mask (bounded logits).
// O written pre-split into g_Obf for out-proj.
// grid = (H, S/128, B): h fastest -> shift/mask L2 reuse across heads.
// ---------------------------------------------------------------------------
#define RSTR 144
#define AOF_KHI 0
#define AOF_KLO 9216
#define AOF_VHI 18432
#define AOF_VLO 27648
#define AOF_QHI 36864
#define AOF_QLO 55296
#define ATT_SMEM 73728

__global__ __launch_bounds__(256, 2) void attn_kernel(const float* __restrict__ shift,
                                                      const float* __restrict__ mask) {
    extern __shared__ char smc[];
    const uint32_t sb = smem_u32(smc);

    const int h  = blockIdx.x;
    const int qt = blockIdx.y;
    const int b  = blockIdx.z;
    const int tid = threadIdx.x;
    const int lane = tid & 31;
    const int w = tid >> 5;
    const int g = lane >> 2;
    const int tg = lane & 3;
    const int r8 = lane & 7;
    const int mlo = (lane >> 3) & 1;
    const int mhi = lane >> 4;

    const float c1  = 0.125f * 1.4426950408889634f;            // log2e / sqrt(64)
    const float hs2 = exp2f(-(float)h) * 1.4426950408889634f;  // head_scale * log2e

    const uint32_t* Qw = g_Qbf + ((size_t)(h * Bb + b) * Ss + qt * 128) * 64;
    const uint32_t* Kw = g_Kbf + ((size_t)(h * Bb + b) * Ss) * 64;
    const uint32_t* Vw = g_Vbf + ((size_t)(h * Bb + b) * Ss) * 64;

    // ---- stage Q once (2048 uint4 = 8 cp.async/thread) ----
#pragma unroll
    for (int it = 0; it < 8; it++) {
        int item = tid + it * 256;
        int row = item >> 4, c4 = item & 15;
        int hi = c4 >> 3;
        cpa16(sb + AOF_QHI + hi * 18432 + (uint32_t)(row * RSTR + (c4 & 7) * 16),
              Qw + row * 64 + c4 * 4);
    }
    CP_COMMIT();

    const uint32_t aQ = sb + AOF_QHI + (uint32_t)((w * 16 + mlo * 8 + r8) * RSTR + mhi * 16);
    const uint32_t aK = sb + AOF_KHI + (uint32_t)((mhi * 8 + r8) * RSTR + mlo * 16);
    const uint32_t aV = sb + AOF_VHI + (uint32_t)((mlo * 8 + r8) * RSTR + mhi * 16);

    float oacc[8][4];
#pragma unroll
    for (int nb = 0; nb < 8; nb++)
#pragma unroll
        for (int q = 0; q < 4; q++) oacc[nb][q] = 0.f;
    float ls0 = 0.f, ls1 = 0.f;

    const int q0 = qt * 128 + w * 16 + g;
    const float* shp = shift + ((size_t)b * Ss + q0) * Ss + 2 * tg;
    const float* mkp = mask  + ((size_t)b * Ss + q0) * Ss + 2 * tg;

#pragma unroll 1
    for (int kt = 0; kt < 32; kt++) {
        __syncthreads();   // previous tile's consumers done
        // ---- stage K,V tile (2048 uint4 = 8 cp.async/thread) ----
#pragma unroll
        for (int it = 0; it < 8; it++) {
            int item = tid + it * 256;
            int side = item >> 10;          // 0 = K, 1 = V
            int idx = item & 1023;
            int row = idx >> 4, c4 = idx & 15;
            int hi = c4 >> 3;
            const uint32_t* src = (side ? Vw : Kw) + kt * 4096 + row * 64 + c4 * 4;
            cpa16(sb + side * 18432 + hi * 9216
                     + (uint32_t)(row * RSTR + (c4 & 7) * 16), src);
        }
        CP_COMMIT();
        CP_WAIT0();
        __syncthreads();

        // ---- S = Q @ K^T (bf16 x3) ----
        float sacc[8][4];
#pragma unroll
        for (int nb = 0; nb < 8; nb++)
#pragma unroll
            for (int q = 0; q < 4; q++) sacc[nb][q] = 0.f;
#pragma unroll
        for (int kk = 0; kk < 4; kk++) {
            uint32_t qh[4], ql[4], kf[4];
            ldsm4(qh, aQ + kk * 32);
            ldsm4(ql, aQ + (AOF_QLO - AOF_QHI) + kk * 32);
#pragma unroll
            for (int nbp = 0; nbp < 4; nbp++) {
                ldsm4(kf, aK + nbp * (16 * RSTR) + kk * 32);
                mma_bf16(sacc[2*nbp],   qh, kf[0], kf[1]);
                mma_bf16(sacc[2*nbp+1], qh, kf[2], kf[3]);
                mma_bf16(sacc[2*nbp],   ql, kf[0], kf[1]);
                mma_bf16(sacc[2*nbp+1], ql, kf[2], kf[3]);
                ldsm4(kf, aK + (AOF_KLO - AOF_KHI) + nbp * (16 * RSTR) + kk * 32);
                mma_bf16(sacc[2*nbp],   qh, kf[0], kf[1]);
                mma_bf16(sacc[2*nbp+1], qh, kf[2], kf[3]);
            }
        }

        // ---- softmax in registers -> P fragments (hi/lo bf16) ----
        uint32_t pah[4][4], pal[4][4];
        const float* sh_r = shp + kt * 64;
        const float* mk_r = mkp + kt * 64;
#pragma unroll
        for (int nb = 0; nb < 8; nb++) {
            float2 sh0 = *(const float2*)(sh_r + nb * 8);
            float2 mk0 = *(const float2*)(mk_r + nb * 8);
            float2 sh1 = *(const float2*)(sh_r + 8 * Ss + nb * 8);
            float2 mk1 = *(const float2*)(mk_r + 8 * Ss + nb * 8);
            float t00 = fmaf(sacc[nb][0], c1, -hs2 * sh0.x);
            float t01 = fmaf(sacc[nb][1], c1, -hs2 * sh0.y);
            float t10 = fmaf(sacc[nb][2], c1, -hs2 * sh1.x);
            float t11 = fmaf(sacc[nb][3], c1, -hs2 * sh1.y);
            float p00 = exp2f(t00) * mk0.x;
            float p01 = exp2f(t01) * mk0.y;
            float p10 = exp2f(t10) * mk1.x;
            float p11 = exp2f(t11) * mk1.y;
            ls0 += p00 + p01;
            ls1 += p10 + p11;
            uint32_t w0 = bf2(p01, p00);
            uint32_t w1 = bf2(p11, p10);
            uint32_t w0l = bf2(p01 - bfhi_f(w0), p00 - bflo_f(w0));
            uint32_t w1l = bf2(p11 - bfhi_f(w1), p10 - bflo_f(w1));
            const int kk2 = nb >> 1;
            if (nb & 1) { pah[kk2][2] = w0; pah[kk2][3] = w1; pal[kk2][2] = w0l; pal[kk2][3] = w1l; }
            else        { pah[kk2][0] = w0; pah[kk2][1] = w1; pal[kk2][0] = w0l; pal[kk2][1] = w1l; }
        }

        // ---- O += P @ V (bf16 x3, V via ldmatrix.trans) ----
#pragma unroll
        for (int kk2 = 0; kk2 < 4; kk2++) {
#pragma unroll
            for (int nbp = 0; nbp < 4; nbp++) {
                uint32_t vf[4];
                ldsm4t(vf, aV + kk2 * (16 * RSTR) + nbp * 32);
                mma_bf16(oacc[2*nbp],   pah[kk2], vf[0], vf[1]);
                mma_bf16(oacc[2*nbp+1], pah[kk2], vf[2], vf[3]);
                mma_bf16(oacc[2*nbp],   pal[kk2], vf[0], vf[1]);
                mma_bf16(oacc[2*nbp+1], pal[kk2], vf[2], vf[3]);
                ldsm4t(vf, aV + (AOF_VLO - AOF_VHI) + kk2 * (16 * RSTR) + nbp * 32);
                mma_bf16(oacc[2*nbp],   pah[kk2], vf[0], vf[1]);
                mma_bf16(oacc[2*nbp+1], pah[kk2], vf[2], vf[3]);
            }
        }
    }

    // ---- epilogue: reduce row sums, scale, write pre-split O ----
    ls0 += __shfl_xor_sync(0xffffffffu, ls0, 1);
    ls0 += __shfl_xor_sync(0xffffffffu, ls0, 2);
    ls1 += __shfl_xor_sync(0xffffffffu, ls1, 1);
    ls1 += __shfl_xor_sync(0xffffffffu, ls1, 2);
    const float i0 = 1.f / ls0;
    const float i1 = 1.f / ls1;

    const size_t base0 = ((size_t)b * Ss + q0) * 512 + h * 32 + tg;
#pragma unroll
    for (int nb = 0; nb < 8; nb++) {
        uint32_t hi, lo;
        split2(make_float2(oacc[nb][0] * i0, oacc[nb][1] * i0), hi, lo);
        g_Obf[base0 + nb * 4] = hi;
        g_Obf[base0 + 256 + nb * 4] = lo;
        split2(make_float2(oacc[nb][2] * i1, oacc[nb][3] * i1), hi, lo);
        g_Obf[base0 + 8 * 512 + nb * 4] = hi;
        g_Obf[base0 + 8 * 512 + 256 + nb * 4] = lo;
    }
}

// ---------------------------------------------------------------------------
extern "C" void kernel_launch(void* const* d_in, const int* in_sizes, int n_in,
                              void* d_out, int out_size) {
    const float* x     = (const float*)d_in[0];
    const float* shift = (const float*)d_in[1];
    const float* mask  = (const float*)d_in[2];
    const float* W     = (const float*)d_in[3];
    const float* b     = (const float*)d_in[4];
    const float* Wo    = (const float*)d_in[5];
    const float* bo    = (const float*)d_in[6];
    float* out = (float*)d_out;

    cudaFuncSetAttribute(tc_gemm<0>, cudaFuncAttributeMaxDynamicSharedMemorySize,
                         GEMM_SMEM);
    cudaFuncSetAttribute(tc_gemm<1>, cudaFuncAttributeMaxDynamicSharedMemorySize,
                         GEMM_SMEM);
    cudaFuncSetAttribute(attn_kernel, cudaFuncAttributeMaxDynamicSharedMemorySize,
                         ATT_SMEM);

    // split X/W/Wo once
    presplit<<<2048, 256>>>(x, W, Wo);

    // QKV projection: M=4096, N=1536, K=512 (bf16x3, pre-split I/O)
    tc_gemm<0><<<dim3(12, 32), 256, GEMM_SMEM>>>(b, nullptr);

    // attention: 128q x 64k tiles (bf16x3, copy-only staging)
    attn_kernel<<<dim3(Hh, Ss / 128, Bb), 256, ATT_SMEM>>>(shift, mask);

    // output projection: M=4096, N=512, K=512 (bf16x3)
    tc_gemm<1><<<dim3(4, 32), 256, GEMM_SMEM>>>(bo, out);
}